// round 13
// baseline (speedup 1.0000x reference)
#include <cuda_runtime.h>
#include <cuda_fp16.h>
#include <math.h>
#include <cstdint>

#define D_MODEL 1024
#define D_FF    4096
#define N_HEADS 16
#define D_HEAD  64
#define BATCH   2
#define SEQ     2048
#define NROWS   (BATCH*SEQ)   /* 4096 */
#define QKVS    (3*D_MODEL)   /* 3072 */

// ---------------- scratch (device globals; no allocation allowed) ----------
__device__ __half g_h    [NROWS * D_MODEL];
__device__ __half g_h2   [NROWS * D_MODEL];
__device__ __half g_at   [NROWS * D_MODEL];
__device__ __half g_ff   [NROWS * D_FF];
__device__ __half g_Bqkv [QKVS * D_MODEL];     // wq(*0.125)|wk|wv rows
__device__ __half g_Bo   [D_MODEL * D_MODEL];
__device__ __half g_B1   [D_FF * D_MODEL];
__device__ __half g_B2   [D_MODEL * D_FF];
__device__ __half g_qkv  [NROWS * QKVS];       // q|k|v packed per row
__device__ float  g_x1   [NROWS * D_MODEL];

// ================= PTX helpers =============================================
__device__ __forceinline__ uint32_t smem_u32(const void* p) {
    uint32_t a;
    asm("{ .reg .u64 t; cvta.to.shared.u64 t, %1; cvt.u32.u64 %0, t; }" : "=r"(a) : "l"(p));
    return a;
}
__device__ __forceinline__ void cp16(uint32_t s, const void* g) {
    asm volatile("cp.async.cg.shared.global [%0], [%1], 16;" :: "r"(s), "l"(g));
}
#define CP_COMMIT() asm volatile("cp.async.commit_group;" ::: "memory")
#define CP_WAIT(n)  asm volatile("cp.async.wait_group %0;" :: "n"(n) : "memory")

#define LDSM4(r, a) \
    asm volatile("ldmatrix.sync.aligned.m8n8.x4.shared.b16 {%0,%1,%2,%3}, [%4];" \
        : "=r"((r)[0]), "=r"((r)[1]), "=r"((r)[2]), "=r"((r)[3]) : "r"(a))
#define LDSM4T(r, a) \
    asm volatile("ldmatrix.sync.aligned.m8n8.x4.trans.shared.b16 {%0,%1,%2,%3}, [%4];" \
        : "=r"((r)[0]), "=r"((r)[1]), "=r"((r)[2]), "=r"((r)[3]) : "r"(a))

#define MMA16816(c, a, b0, b1) \
    asm volatile("mma.sync.aligned.m16n8k16.row.col.f32.f16.f16.f32 " \
        "{%0,%1,%2,%3}, {%4,%5,%6,%7}, {%8,%9}, {%0,%1,%2,%3};" \
        : "+f"((c)[0]), "+f"((c)[1]), "+f"((c)[2]), "+f"((c)[3]) \
        : "r"((a)[0]), "r"((a)[1]), "r"((a)[2]), "r"((a)[3]), "r"(b0), "r"(b1))

// - GEMM tiling: BM=128, BN=256, BK=32, warp tile 64x64, 8 warps, 3 stages --
#define BM 128
#define BN 256
#define BK 32
#define GRS 80                             /* smem row stride bytes (40 fp16) */
#define GTA (128 * GRS)                    /* A tile: 10240 B */
#define GTB (256 * GRS)                    /* B tile: 20480 B */
#define GSTAGEB (GTA + GTB)                /* 30720 B */
#define SMEM_GEMM_BYTES (3 * GSTAGEB)      /* 92160 B */

__device__ __forceinline__ float gelu_exact(float v) {
    return 0.5f * v * (1.0f + erff(v * 0.70710678118654752f));
}

// ===== HMMA GEMM: C[M,N] = A[M,K] * B[N,K]^T  (fp16 in, fp32 accum) ========
// EPI: 1 +res->fp32, 2 gelu(+bias)->fp16, 3 +bias+res->fp32, 4 ->fp16
template<int EPI>
__global__ __launch_bounds__(256, 1) void hmma_gemm(
    const __half* __restrict__ A,
    const __half* __restrict__ B,
    const float* __restrict__ bias,
    const float* __restrict__ res,
    float* __restrict__ C,
    __half* __restrict__ CH,
    int N, int K)
{
    extern __shared__ char smem[];
    const uint32_t sbase = smem_u32(smem);
    const int tid  = threadIdx.x;
    const int wid  = tid >> 5, lane = tid & 31;
    const int wm   = wid >> 2, wn = wid & 3;       // 2 x 4 warps, 64x64 tiles
    const int rowB = blockIdx.y * BM, colB = blockIdx.x * BN;

    const __half* Ag = A + (size_t)rowB * K;
    const __half* Bg = B + (size_t)colB * K;

    auto load_stage = [&](int s, int kt) {
        const int k0 = kt * BK;
        const uint32_t st = sbase + s * GSTAGEB;
        #pragma unroll
        for (int i = 0; i < 2; i++) {               // A: 512 chunks (128r x 4)
            const int c = i * 256 + tid;
            const int r = c >> 2, seg = c & 3;
            cp16(st + r * GRS + seg * 16, Ag + (size_t)r * K + k0 + seg * 8);
        }
        #pragma unroll
        for (int i = 0; i < 4; i++) {               // B: 1024 chunks (256r x 4)
            const int c = i * 256 + tid;
            const int r = c >> 2, seg = c & 3;
            cp16(st + GTA + r * GRS + seg * 16, Bg + (size_t)r * K + k0 + seg * 8);
        }
        CP_COMMIT();
    };

    float acc[4][8][4];
    #pragma unroll
    for (int i = 0; i < 4; i++)
        #pragma unroll
        for (int j = 0; j < 8; j++)
            #pragma unroll
            for (int q = 0; q < 4; q++) acc[i][j][q] = 0.0f;

    const int niter = K / BK;
    load_stage(0, 0);
    load_stage(1, 1);

    for (int t = 0; t < niter; t++) {
        CP_WAIT(1);
        __syncthreads();
        if (t + 2 < niter) load_stage((t + 2) % 3, t + 2);

        const uint32_t st = sbase + (t % 3) * GSTAGEB;
        const uint32_t sA = st, sB = st + GTA;

        #pragma unroll
        for (int ks = 0; ks < 2; ks++) {
            const uint32_t aoff = (wm*64 + (lane & 15)) * GRS
                                + (ks*16 + (lane >> 4) * 8) * 2;
            const uint32_t boff = (wn*64 + (lane >> 4) * 8 + (lane & 7)) * GRS
                                + (ks*16 + ((lane >> 3) & 1) * 8) * 2;
            uint32_t a[4][4], b[4][4];
            #pragma unroll
            for (int mi = 0; mi < 4; mi++) LDSM4(a[mi], sA + aoff + mi*16*GRS);
            #pragma unroll
            for (int nt = 0; nt < 4; nt++) LDSM4(b[nt], sB + boff + nt*16*GRS);
            #pragma unroll
            for (int mi = 0; mi < 4; mi++)
                #pragma unroll
                for (int nt = 0; nt < 4; nt++) {
                    MMA16816(acc[mi][nt*2+0], a[mi], b[nt][0], b[nt][1]);
                    MMA16816(acc[mi][nt*2+1], a[mi], b[nt][2], b[nt][3]);
                }
        }
    }

    const int g  = lane >> 2;
    const int tq = lane & 3;
    #pragma unroll
    for (int mi = 0; mi < 4; mi++) {
        #pragma unroll
        for (int half = 0; half < 2; half++) {
            const int gr = rowB + wm*64 + mi*16 + g + half*8;
            #pragma unroll
            for (int ni = 0; ni < 8; ni++) {
                const int gc = colB + wn*64 + ni*8 + tq*2;
                float v0 = acc[mi][ni][half*2+0];
                float v1 = acc[mi][ni][half*2+1];
                if (EPI == 1) {
                    const float2 r2 = *reinterpret_cast<const float2*>(res + (size_t)gr * N + gc);
                    *reinterpret_cast<float2*>(C + (size_t)gr * N + gc) =
                        make_float2(v0 + r2.x, v1 + r2.y);
                } else if (EPI == 3) {
                    const float2 r2 = *reinterpret_cast<const float2*>(res + (size_t)gr * N + gc);
                    *reinterpret_cast<float2*>(C + (size_t)gr * N + gc) =
                        make_float2(v0 + bias[gc] + r2.x, v1 + bias[gc + 1] + r2.y);
                } else {
                    float s0 = v0, s1 = v1;
                    if (EPI == 2) {
                        s0 = gelu_exact(v0 + bias[gc]);
                        s1 = gelu_exact(v1 + bias[gc + 1]);
                    }
                    __half2 h2v;
                    h2v.x = __float2half(s0);
                    h2v.y = __float2half(s1);
                    *reinterpret_cast<__half2*>(CH + (size_t)gr * N + gc) = h2v;
                }
            }
        }
    }
}

// ---------------- layernorm -> fp16 ----------------------------------------
__global__ __launch_bounds__(256) void ln_half(const float* __restrict__ x,
        const float* __restrict__ g, const float* __restrict__ b,
        __half* __restrict__ H)
{
    __shared__ float red[256];
    const int row = blockIdx.x, t = threadIdx.x;
    const float4 v = reinterpret_cast<const float4*>(x + (size_t)row * D_MODEL)[t];
    red[t] = v.x + v.y + v.z + v.w;
    __syncthreads();
    #pragma unroll
    for (int o = 128; o > 0; o >>= 1) { if (t < o) red[t] += red[t + o]; __syncthreads(); }
    const float mu = red[0] * (1.0f / D_MODEL);
    __syncthreads();
    const float dx = v.x - mu, dy = v.y - mu, dz = v.z - mu, dw = v.w - mu;
    red[t] = dx*dx + dy*dy + dz*dz + dw*dw;
    __syncthreads();
    #pragma unroll
    for (int o = 128; o > 0; o >>= 1) { if (t < o) red[t] += red[t + o]; __syncthreads(); }
    const float rs = rsqrtf(red[0] * (1.0f / D_MODEL) + 1e-5f);
    const float4 gv = reinterpret_cast<const float4*>(g)[t];
    const float4 bv = reinterpret_cast<const float4*>(b)[t];
    __half h[4] = {
        __float2half(dx*rs*gv.x + bv.x), __float2half(dy*rs*gv.y + bv.y),
        __float2half(dz*rs*gv.z + bv.z), __float2half(dw*rs*gv.w + bv.w) };
    *reinterpret_cast<uint2*>(H + (size_t)row * D_MODEL + t * 4) =
        *reinterpret_cast<uint2*>(h);
}

// ---------------- fp32 -> fp16 converters ----------------------------------
__global__ __launch_bounds__(256) void conv_single(const float* __restrict__ src,
        __half* __restrict__ H, int total)
{
    const int i4 = blockIdx.x * 256 + threadIdx.x;
    if (i4 * 4 >= total) return;
    const float4 v = reinterpret_cast<const float4*>(src)[i4];
    __half h[4] = { __float2half(v.x), __float2half(v.y),
                    __float2half(v.z), __float2half(v.w) };
    *reinterpret_cast<uint2*>(H + (size_t)i4 * 4) = *reinterpret_cast<uint2*>(h);
}

// wq (scaled 0.125) | wk | wv -> one [3072 x 1024] fp16 buffer
__global__ __launch_bounds__(256) void conv_qkv(const float* __restrict__ wq,
        const float* __restrict__ wk, const float* __restrict__ wv,
        __half* __restrict__ dst)
{
    const int y = blockIdx.y;
    const float* src = (y == 0) ? wq : ((y == 1) ? wk : wv);
    const float sc = (y == 0) ? 0.125f : 1.0f;
    const int i4 = blockIdx.x * 256 + threadIdx.x;   // 1M/4 elems
    const float4 v = reinterpret_cast<const float4*>(src)[i4];
    __half h[4] = { __float2half(v.x * sc), __float2half(v.y * sc),
                    __float2half(v.z * sc), __float2half(v.w * sc) };
    *reinterpret_cast<uint2*>(dst + (size_t)y * D_MODEL * D_MODEL + (size_t)i4 * 4) =
        *reinterpret_cast<uint2*>(h);
}

// ========== flash attention (fp16, BQ=64, TK=64, 4 warps) ==================
// reads q/k/v from packed [NROWS x 3072] buffer
#define FSTRIDE 144
#define FTILEB  (64 * FSTRIDE)         /* 9216 */
#define FQ_BYTES (FTILEB)
#define FKV_BYTES (2 * FTILEB)
#define SMEM_FLASH_BYTES (FQ_BYTES + 2 * FKV_BYTES)  /* 46080 */

__global__ __launch_bounds__(128, 2) void flash_mma(
        const __half* __restrict__ QKV, __half* __restrict__ outH)
{
    extern __shared__ char smem[];
    const uint32_t sb = smem_u32(smem);
    const int tid = threadIdx.x;
    const int w = tid >> 5, lane = tid & 31;
    const int bh = blockIdx.y;                       // 0..31
    const size_t base = (size_t)(bh >> 4) * SEQ * QKVS + (size_t)(bh & 15) * D_HEAD;
    const int qb = blockIdx.x * 64;

    #pragma unroll
    for (int i = 0; i < 4; i++) {
        const int c = i * 128 + tid;
        const int row = c >> 3, seg = c & 7;
        cp16(sb + row * FSTRIDE + seg * 16,
             QKV + base + (size_t)(qb + row) * QKVS + seg * 8);
    }
    auto load_kv = [&](int buf, int kt) {
        const uint32_t kvb = sb + FQ_BYTES + buf * FKV_BYTES;
        #pragma unroll
        for (int i = 0; i < 4; i++) {
            const int c = i * 128 + tid;
            const int row = c >> 3, seg = c & 7;
            const size_t goff = base + (size_t)(kt + row) * QKVS + seg * 8;
            const uint32_t soff = row * FSTRIDE + seg * 16;
            cp16(kvb + 0*FTILEB + soff, QKV + goff + D_MODEL);       // K
            cp16(kvb + 1*FTILEB + soff, QKV + goff + 2 * D_MODEL);   // V
        }
        CP_COMMIT();
    };
    load_kv(0, 0);

    float m0 = -1e30f, m1 = -1e30f, l0 = 0.0f, l1 = 0.0f;
    float o[8][4];
    #pragma unroll
    for (int j = 0; j < 8; j++)
        #pragma unroll
        for (int q = 0; q < 4; q++) o[j][q] = 0.0f;

    const uint32_t aQrow = (w*16 + (lane & 15)) * FSTRIDE + (lane >> 4) * 16;
    const uint32_t bKrow = ((lane >> 4) * 8 + (lane & 7)) * FSTRIDE + ((lane >> 3) & 1) * 16;
    const uint32_t bVrow = (lane & 15) * FSTRIDE + (lane >> 4) * 16;

    uint32_t qf[4][4];

    for (int ti = 0; ti < SEQ / 64; ti++) {
        CP_WAIT(0);
        __syncthreads();
        if (ti + 1 < SEQ / 64) load_kv((ti + 1) & 1, (ti + 1) * 64);
        if (ti == 0) {
            #pragma unroll
            for (int ks = 0; ks < 4; ks++) LDSM4(qf[ks], sb + aQrow + ks * 32);
        }
        const uint32_t kvb = sb + FQ_BYTES + (ti & 1) * FKV_BYTES;

        float s[8][4];
        #pragma unroll
        for (int j = 0; j < 8; j++)
            #pragma unroll
            for (int q = 0; q < 4; q++) s[j][q] = 0.0f;
        #pragma unroll
        for (int ks = 0; ks < 4; ks++) {
            uint32_t bkh[4][4];
            #pragma unroll
            for (int nt = 0; nt < 4; nt++)
                LDSM4(bkh[nt], kvb + bKrow + (nt*16) * FSTRIDE + ks * 32);
            #pragma unroll
            for (int nt = 0; nt < 4; nt++) {
                MMA16816(s[nt*2+0], qf[ks], bkh[nt][0], bkh[nt][1]);
                MMA16816(s[nt*2+1], qf[ks], bkh[nt][2], bkh[nt][3]);
            }
        }

        float mx0 = -1e30f, mx1 = -1e30f;
        #pragma unroll
        for (int j = 0; j < 8; j++) {
            mx0 = fmaxf(mx0, fmaxf(s[j][0], s[j][1]));
            mx1 = fmaxf(mx1, fmaxf(s[j][2], s[j][3]));
        }
        mx0 = fmaxf(mx0, __shfl_xor_sync(0xffffffffu, mx0, 1));
        mx0 = fmaxf(mx0, __shfl_xor_sync(0xffffffffu, mx0, 2));
        mx1 = fmaxf(mx1, __shfl_xor_sync(0xffffffffu, mx1, 1));
        mx1 = fmaxf(mx1, __shfl_xor_sync(0xffffffffu, mx1, 2));
        const float mn0 = fmaxf(m0, mx0), mn1 = fmaxf(m1, mx1);
        const float corr0 = __expf(m0 - mn0), corr1 = __expf(m1 - mn1);
        m0 = mn0; m1 = mn1;

        float sum0 = 0.0f, sum1 = 0.0f;
        uint32_t ap[16];
        #pragma unroll
        for (int j = 0; j < 8; j++) {
            float p0 = __expf(s[j][0] - mn0), p1 = __expf(s[j][1] - mn0);
            float p2 = __expf(s[j][2] - mn1), p3 = __expf(s[j][3] - mn1);
            sum0 += p0 + p1; sum1 += p2 + p3;
            __half2 hi01 = __halves2half2(__float2half(p0), __float2half(p1));
            __half2 hi23 = __halves2half2(__float2half(p2), __float2half(p3));
            const int t4 = (j >> 1) * 4 + (j & 1) * 2;
            ap[t4 + 0] = *reinterpret_cast<uint32_t*>(&hi01);
            ap[t4 + 1] = *reinterpret_cast<uint32_t*>(&hi23);
        }
        sum0 += __shfl_xor_sync(0xffffffffu, sum0, 1);
        sum0 += __shfl_xor_sync(0xffffffffu, sum0, 2);
        sum1 += __shfl_xor_sync(0xffffffffu, sum1, 1);
        sum1 += __shfl_xor_sync(0xffffffffu, sum1, 2);
        l0 = l0 * corr0 + sum0;
        l1 = l1 * corr1 + sum1;
        #pragma unroll
        for (int j = 0; j < 8; j++) {
            o[j][0] *= corr0; o[j][1] *= corr0;
            o[j][2] *= corr1; o[j][3] *= corr1;
        }

        #pragma unroll
        for (int t = 0; t < 4; t++) {
            uint32_t bvh[4][4];
            #pragma unroll
            for (int ns = 0; ns < 4; ns++)
                LDSM4T(bvh[ns], kvb + FTILEB + bVrow + (t*16) * FSTRIDE + ns * 32);
            #pragma unroll
            for (int ns = 0; ns < 4; ns++) {
                MMA16816(o[ns*2+0], ap + t*4, bvh[ns][0], bvh[ns][1]);
                MMA16816(o[ns*2+1], ap + t*4, bvh[ns][2], bvh[ns][3]);
            }
        }
    }

    const float inv0 = 1.0f / l0, inv1 = 1.0f / l1;
    const int r0 = qb + w*16 + (lane >> 2);
    const int gr0 = (bh >> 4) * SEQ + r0;
    const int colb = (bh & 15) * D_HEAD + 2 * (lane & 3);
    #pragma unroll
    for (int j = 0; j < 8; j++) {
        const int col = colb + j * 8;
        __half2 h0, h1;
        h0.x = __float2half(o[j][0] * inv0);
        h0.y = __float2half(o[j][1] * inv0);
        h1.x = __float2half(o[j][2] * inv1);
        h1.y = __float2half(o[j][3] * inv1);
        *reinterpret_cast<__half2*>(outH + (size_t)gr0 * D_MODEL + col) = h0;
        *reinterpret_cast<__half2*>(outH + (size_t)(gr0 + 8) * D_MODEL + col) = h1;
    }
}

// ---------------- launch --------------------------------------------------
extern "C" void kernel_launch(void* const* d_in, const int* in_sizes, int n_in,
                              void* d_out, int out_size)
{
    const float* x    = (const float*)d_in[0];
    const float* wq   = (const float*)d_in[1];
    const float* wk   = (const float*)d_in[2];
    const float* wv   = (const float*)d_in[3];
    const float* wo   = (const float*)d_in[4];
    const float* w1   = (const float*)d_in[5];
    const float* b1   = (const float*)d_in[6];
    const float* w2   = (const float*)d_in[7];
    const float* b2   = (const float*)d_in[8];
    const float* ln1g = (const float*)d_in[9];
    const float* ln1b = (const float*)d_in[10];
    const float* ln2g = (const float*)d_in[11];
    const float* ln2b = (const float*)d_in[12];
    float* out = (float*)d_out;

    __half *h, *h2, *at, *ff, *Bqkv, *Bo, *B1, *B2, *qkv;
    float *x1;
    cudaGetSymbolAddress((void**)&h,    g_h);
    cudaGetSymbolAddress((void**)&h2,   g_h2);
    cudaGetSymbolAddress((void**)&at,   g_at);
    cudaGetSymbolAddress((void**)&ff,   g_ff);
    cudaGetSymbolAddress((void**)&Bqkv, g_Bqkv);
    cudaGetSymbolAddress((void**)&Bo,   g_Bo);
    cudaGetSymbolAddress((void**)&B1,   g_B1);
    cudaGetSymbolAddress((void**)&B2,   g_B2);
    cudaGetSymbolAddress((void**)&qkv,  g_qkv);
    cudaGetSymbolAddress((void**)&x1,   g_x1);

    cudaFuncSetAttribute(hmma_gemm<1>, cudaFuncAttributeMaxDynamicSharedMemorySize, SMEM_GEMM_BYTES);
    cudaFuncSetAttribute(hmma_gemm<2>, cudaFuncAttributeMaxDynamicSharedMemorySize, SMEM_GEMM_BYTES);
    cudaFuncSetAttribute(hmma_gemm<3>, cudaFuncAttributeMaxDynamicSharedMemorySize, SMEM_GEMM_BYTES);
    cudaFuncSetAttribute(hmma_gemm<4>, cudaFuncAttributeMaxDynamicSharedMemorySize, SMEM_GEMM_BYTES);
    cudaFuncSetAttribute(flash_mma,    cudaFuncAttributeMaxDynamicSharedMemorySize, SMEM_FLASH_BYTES);

    const dim3 blkG(256);
    const dim3 blk(256);
    const dim3 gQKV(QKVS/BN,    NROWS/BM);   // (12, 32) = 384 CTAs
    const dim3 gP  (D_MODEL/BN, NROWS/BM);   // (4, 32)  = 128 CTAs
    const dim3 gF1 (D_FF/BN,    NROWS/BM);   // (16, 32) = 512 CTAs
    const dim3 gAttn(SEQ/64, BATCH*N_HEADS); // (32, 32)

    conv_qkv<<<dim3(D_MODEL*D_MODEL/4/256, 3), blk>>>(wq, wk, wv, Bqkv);             // 1
    ln_half<<<NROWS, blk>>>(x, ln1g, ln1b, h);                                       // 2
    conv_single<<<(D_FF*D_MODEL/4+255)/256, blk>>>(w1, B1, D_FF*D_MODEL);            // 3
    hmma_gemm<4><<<gQKV, blkG, SMEM_GEMM_BYTES>>>(h, Bqkv, nullptr, nullptr,
                                                  nullptr, qkv, QKVS, D_MODEL);      // 4 <- profiled
    conv_single<<<(D_MODEL*D_MODEL/4+255)/256, blk>>>(wo, Bo, D_MODEL*D_MODEL);      // 5
    conv_single<<<(D_MODEL*D_FF/4+255)/256,    blk>>>(w2, B2, D_MODEL*D_FF);         // 6
    flash_mma<<<gAttn, dim3(128), SMEM_FLASH_BYTES>>>(qkv, at);                      // 7
    hmma_gemm<1><<<gP, blkG, SMEM_GEMM_BYTES>>>(at, Bo, nullptr, x, x1,
                                               nullptr, D_MODEL, D_MODEL);           // 8
    ln_half<<<NROWS, blk>>>(x1, ln2g, ln2b, h2);                                     // 9
    hmma_gemm<2><<<gF1, blkG, SMEM_GEMM_BYTES>>>(h2, B1, b1, nullptr, nullptr,
                                               ff, D_FF, D_MODEL);                   // 10
    hmma_gemm<3><<<gP, blkG, SMEM_GEMM_BYTES>>>(ff, B2, b2, x1, out,
                                               nullptr, D_MODEL, D_FF);              // 11
}

// round 14
// speedup vs baseline: 1.0761x; 1.0761x over previous
#include <cuda_runtime.h>
#include <cuda_fp16.h>
#include <math.h>
#include <cstdint>

#define D_MODEL 1024
#define D_FF    4096
#define N_HEADS 16
#define D_HEAD  64
#define BATCH   2
#define SEQ     2048
#define NROWS   (BATCH*SEQ)   /* 4096 */
#define QKVS    (3*D_MODEL)   /* 3072 */

// ---------------- scratch (device globals; no allocation allowed) ----------
__device__ __half g_h    [NROWS * D_MODEL];
__device__ __half g_h2   [NROWS * D_MODEL];
__device__ __half g_at   [NROWS * D_MODEL];
__device__ __half g_ff   [NROWS * D_FF];
__device__ __half g_Bqkv [QKVS * D_MODEL];     // wq(*0.125)|wk|wv rows
__device__ __half g_Bo   [D_MODEL * D_MODEL];
__device__ __half g_B1   [D_FF * D_MODEL];
__device__ __half g_B2   [D_MODEL * D_FF];
__device__ __half g_qkv  [NROWS * QKVS];       // q|k|v packed per row
__device__ float  g_x1   [NROWS * D_MODEL];

// ================= PTX helpers =============================================
__device__ __forceinline__ uint32_t smem_u32(const void* p) {
    uint32_t a;
    asm("{ .reg .u64 t; cvta.to.shared.u64 t, %1; cvt.u32.u64 %0, t; }" : "=r"(a) : "l"(p));
    return a;
}
__device__ __forceinline__ void cp16(uint32_t s, const void* g) {
    asm volatile("cp.async.cg.shared.global [%0], [%1], 16;" :: "r"(s), "l"(g));
}
#define CP_COMMIT() asm volatile("cp.async.commit_group;" ::: "memory")
#define CP_WAIT(n)  asm volatile("cp.async.wait_group %0;" :: "n"(n) : "memory")

#define LDSM4(r, a) \
    asm volatile("ldmatrix.sync.aligned.m8n8.x4.shared.b16 {%0,%1,%2,%3}, [%4];" \
        : "=r"((r)[0]), "=r"((r)[1]), "=r"((r)[2]), "=r"((r)[3]) : "r"(a))
#define LDSM4T(r, a) \
    asm volatile("ldmatrix.sync.aligned.m8n8.x4.trans.shared.b16 {%0,%1,%2,%3}, [%4];" \
        : "=r"((r)[0]), "=r"((r)[1]), "=r"((r)[2]), "=r"((r)[3]) : "r"(a))

#define MMA16816(c, a, b0, b1) \
    asm volatile("mma.sync.aligned.m16n8k16.row.col.f32.f16.f16.f32 " \
        "{%0,%1,%2,%3}, {%4,%5,%6,%7}, {%8,%9}, {%0,%1,%2,%3};" \
        : "+f"((c)[0]), "+f"((c)[1]), "+f"((c)[2]), "+f"((c)[3]) \
        : "r"((a)[0]), "r"((a)[1]), "r"((a)[2]), "r"((a)[3]), "r"(b0), "r"(b1))

// -- GEMM tiling (R12): BM=BN=128, BK=32, 3 stages, 8 warps 2x4, 64x32 tiles
#define BM 128
#define BN 128
#define BK 32
#define GRS 80                             /* smem row stride bytes (40 fp16) */
#define GT  (128 * GRS)                    /* one tile: 10240 B */
#define GSTAGEB (2 * GT)                   /* A,B: 20480 B */
#define SMEM_GEMM_BYTES (3 * GSTAGEB)      /* 61440 B */

__device__ __forceinline__ float gelu_exact(float v) {
    return 0.5f * v * (1.0f + erff(v * 0.70710678118654752f));
}

// ===== HMMA GEMM: C[M,N] = A[M,K] * B[N,K]^T  (fp16 in, fp32 accum) ========
// EPI: 1 +res->fp32, 2 gelu(+bias)->fp16, 3 +bias+res->fp32, 4 ->fp16
template<int EPI>
__global__ __launch_bounds__(256, 2) void hmma_gemm(
    const __half* __restrict__ A,
    const __half* __restrict__ B,
    const float* __restrict__ bias,
    const float* __restrict__ res,
    float* __restrict__ C,
    __half* __restrict__ CH,
    int N, int K)
{
    extern __shared__ char smem[];
    const uint32_t sbase = smem_u32(smem);
    const int tid  = threadIdx.x;
    const int wid  = tid >> 5, lane = tid & 31;
    const int wm   = wid >> 2, wn = wid & 3;       // 2 x 4 warps, 64x32 tiles
    const int rowB = blockIdx.y * BM, colB = blockIdx.x * BN;

    const __half* srcs[2] = { A + (size_t)rowB * K, B + (size_t)colB * K };

    auto load_stage = [&](int s, int kt) {
        const int k0 = kt * BK;
        const uint32_t st = sbase + s * GSTAGEB;
        #pragma unroll
        for (int i = 0; i < 4; i++) {
            const int tile = i >> 1;                  // 0..1
            const int within = ((i & 1) << 8) + tid;  // 0..511
            const int r = within >> 2, seg = within & 3;
            cp16(st + tile * GT + r * GRS + seg * 16,
                 srcs[tile] + (size_t)r * K + k0 + seg * 8);
        }
        CP_COMMIT();
    };

    float acc[4][4][4];
    #pragma unroll
    for (int i = 0; i < 4; i++)
        #pragma unroll
        for (int j = 0; j < 4; j++)
            #pragma unroll
            for (int q = 0; q < 4; q++) acc[i][j][q] = 0.0f;

    const int niter = K / BK;
    load_stage(0, 0);
    load_stage(1, 1);

    for (int t = 0; t < niter; t++) {
        CP_WAIT(1);
        __syncthreads();
        if (t + 2 < niter) load_stage((t + 2) % 3, t + 2);

        const uint32_t st = sbase + (t % 3) * GSTAGEB;
        const uint32_t sA = st, sB = st + GT;

        #pragma unroll
        for (int ks = 0; ks < 2; ks++) {
            const uint32_t aoff = (wm*64 + (lane & 15)) * GRS
                                + (ks*16 + (lane >> 4) * 8) * 2;
            const uint32_t boff = (wn*32 + (lane >> 4) * 8 + (lane & 7)) * GRS
                                + (ks*16 + ((lane >> 3) & 1) * 8) * 2;
            uint32_t a[4][4], b[2][4];
            #pragma unroll
            for (int mi = 0; mi < 4; mi++) LDSM4(a[mi], sA + aoff + mi*16*GRS);
            #pragma unroll
            for (int nt = 0; nt < 2; nt++) LDSM4(b[nt], sB + boff + nt*16*GRS);
            #pragma unroll
            for (int mi = 0; mi < 4; mi++)
                #pragma unroll
                for (int nt = 0; nt < 2; nt++) {
                    MMA16816(acc[mi][nt*2+0], a[mi], b[nt][0], b[nt][1]);
                    MMA16816(acc[mi][nt*2+1], a[mi], b[nt][2], b[nt][3]);
                }
        }
        __syncthreads();
    }

    const int g  = lane >> 2;
    const int tq = lane & 3;
    #pragma unroll
    for (int mi = 0; mi < 4; mi++) {
        #pragma unroll
        for (int half = 0; half < 2; half++) {
            const int gr = rowB + wm*64 + mi*16 + g + half*8;
            #pragma unroll
            for (int ni = 0; ni < 4; ni++) {
                const int gc = colB + wn*32 + ni*8 + tq*2;
                float v0 = acc[mi][ni][half*2+0];
                float v1 = acc[mi][ni][half*2+1];
                if (EPI == 1) {
                    const float2 r2 = *reinterpret_cast<const float2*>(res + (size_t)gr * N + gc);
                    *reinterpret_cast<float2*>(C + (size_t)gr * N + gc) =
                        make_float2(v0 + r2.x, v1 + r2.y);
                } else if (EPI == 3) {
                    const float2 r2 = *reinterpret_cast<const float2*>(res + (size_t)gr * N + gc);
                    *reinterpret_cast<float2*>(C + (size_t)gr * N + gc) =
                        make_float2(v0 + bias[gc] + r2.x, v1 + bias[gc + 1] + r2.y);
                } else {
                    float s0 = v0, s1 = v1;
                    if (EPI == 2) {
                        s0 = gelu_exact(v0 + bias[gc]);
                        s1 = gelu_exact(v1 + bias[gc + 1]);
                    }
                    __half2 h2v;
                    h2v.x = __float2half(s0);
                    h2v.y = __float2half(s1);
                    *reinterpret_cast<__half2*>(CH + (size_t)gr * N + gc) = h2v;
                }
            }
        }
    }
}

// ---------------- layernorm -> fp16 ----------------------------------------
__global__ __launch_bounds__(256) void ln_half(const float* __restrict__ x,
        const float* __restrict__ g, const float* __restrict__ b,
        __half* __restrict__ H)
{
    __shared__ float red[256];
    const int row = blockIdx.x, t = threadIdx.x;
    const float4 v = reinterpret_cast<const float4*>(x + (size_t)row * D_MODEL)[t];
    red[t] = v.x + v.y + v.z + v.w;
    __syncthreads();
    #pragma unroll
    for (int o = 128; o > 0; o >>= 1) { if (t < o) red[t] += red[t + o]; __syncthreads(); }
    const float mu = red[0] * (1.0f / D_MODEL);
    __syncthreads();
    const float dx = v.x - mu, dy = v.y - mu, dz = v.z - mu, dw = v.w - mu;
    red[t] = dx*dx + dy*dy + dz*dz + dw*dw;
    __syncthreads();
    #pragma unroll
    for (int o = 128; o > 0; o >>= 1) { if (t < o) red[t] += red[t + o]; __syncthreads(); }
    const float rs = rsqrtf(red[0] * (1.0f / D_MODEL) + 1e-5f);
    const float4 gv = reinterpret_cast<const float4*>(g)[t];
    const float4 bv = reinterpret_cast<const float4*>(b)[t];
    __half h[4] = {
        __float2half(dx*rs*gv.x + bv.x), __float2half(dy*rs*gv.y + bv.y),
        __float2half(dz*rs*gv.z + bv.z), __float2half(dw*rs*gv.w + bv.w) };
    *reinterpret_cast<uint2*>(H + (size_t)row * D_MODEL + t * 4) =
        *reinterpret_cast<uint2*>(h);
}

// ---------------- fp32 -> fp16 converters ----------------------------------
__global__ __launch_bounds__(256) void conv_single(const float* __restrict__ src,
        __half* __restrict__ H, int total)
{
    const int i4 = blockIdx.x * 256 + threadIdx.x;
    if (i4 * 4 >= total) return;
    const float4 v = reinterpret_cast<const float4*>(src)[i4];
    __half h[4] = { __float2half(v.x), __float2half(v.y),
                    __float2half(v.z), __float2half(v.w) };
    *reinterpret_cast<uint2*>(H + (size_t)i4 * 4) = *reinterpret_cast<uint2*>(h);
}

// wq (scaled 0.125) | wk | wv -> one [3072 x 1024] fp16 buffer
__global__ __launch_bounds__(256) void conv_qkv(const float* __restrict__ wq,
        const float* __restrict__ wk, const float* __restrict__ wv,
        __half* __restrict__ dst)
{
    const int y = blockIdx.y;
    const float* src = (y == 0) ? wq : ((y == 1) ? wk : wv);
    const float sc = (y == 0) ? 0.125f : 1.0f;
    const int i4 = blockIdx.x * 256 + threadIdx.x;   // 1M/4 elems
    const float4 v = reinterpret_cast<const float4*>(src)[i4];
    __half h[4] = { __float2half(v.x * sc), __float2half(v.y * sc),
                    __float2half(v.z * sc), __float2half(v.w * sc) };
    *reinterpret_cast<uint2*>(dst + (size_t)y * D_MODEL * D_MODEL + (size_t)i4 * 4) =
        *reinterpret_cast<uint2*>(h);
}

// ========== flash attention (fp16, BQ=64, TK=64, 4 warps) ==================
// reads q/k/v from packed [NROWS x 3072] buffer
#define FSTRIDE 144
#define FTILEB  (64 * FSTRIDE)         /* 9216 */
#define FQ_BYTES (FTILEB)
#define FKV_BYTES (2 * FTILEB)
#define SMEM_FLASH_BYTES (FQ_BYTES + 2 * FKV_BYTES)  /* 46080 */

__global__ __launch_bounds__(128, 2) void flash_mma(
        const __half* __restrict__ QKV, __half* __restrict__ outH)
{
    extern __shared__ char smem[];
    const uint32_t sb = smem_u32(smem);
    const int tid = threadIdx.x;
    const int w = tid >> 5, lane = tid & 31;
    const int bh = blockIdx.y;                       // 0..31
    const size_t base = (size_t)(bh >> 4) * SEQ * QKVS + (size_t)(bh & 15) * D_HEAD;
    const int qb = blockIdx.x * 64;

    #pragma unroll
    for (int i = 0; i < 4; i++) {
        const int c = i * 128 + tid;
        const int row = c >> 3, seg = c & 7;
        cp16(sb + row * FSTRIDE + seg * 16,
             QKV + base + (size_t)(qb + row) * QKVS + seg * 8);
    }
    auto load_kv = [&](int buf, int kt) {
        const uint32_t kvb = sb + FQ_BYTES + buf * FKV_BYTES;
        #pragma unroll
        for (int i = 0; i < 4; i++) {
            const int c = i * 128 + tid;
            const int row = c >> 3, seg = c & 7;
            const size_t goff = base + (size_t)(kt + row) * QKVS + seg * 8;
            const uint32_t soff = row * FSTRIDE + seg * 16;
            cp16(kvb + 0*FTILEB + soff, QKV + goff + D_MODEL);       // K
            cp16(kvb + 1*FTILEB + soff, QKV + goff + 2 * D_MODEL);   // V
        }
        CP_COMMIT();
    };
    load_kv(0, 0);

    float m0 = -1e30f, m1 = -1e30f, l0 = 0.0f, l1 = 0.0f;
    float o[8][4];
    #pragma unroll
    for (int j = 0; j < 8; j++)
        #pragma unroll
        for (int q = 0; q < 4; q++) o[j][q] = 0.0f;

    const uint32_t aQrow = (w*16 + (lane & 15)) * FSTRIDE + (lane >> 4) * 16;
    const uint32_t bKrow = ((lane >> 4) * 8 + (lane & 7)) * FSTRIDE + ((lane >> 3) & 1) * 16;
    const uint32_t bVrow = (lane & 15) * FSTRIDE + (lane >> 4) * 16;

    uint32_t qf[4][4];

    for (int ti = 0; ti < SEQ / 64; ti++) {
        CP_WAIT(0);
        __syncthreads();
        if (ti + 1 < SEQ / 64) load_kv((ti + 1) & 1, (ti + 1) * 64);
        if (ti == 0) {
            #pragma unroll
            for (int ks = 0; ks < 4; ks++) LDSM4(qf[ks], sb + aQrow + ks * 32);
        }
        const uint32_t kvb = sb + FQ_BYTES + (ti & 1) * FKV_BYTES;

        float s[8][4];
        #pragma unroll
        for (int j = 0; j < 8; j++)
            #pragma unroll
            for (int q = 0; q < 4; q++) s[j][q] = 0.0f;
        #pragma unroll
        for (int ks = 0; ks < 4; ks++) {
            uint32_t bkh[4][4];
            #pragma unroll
            for (int nt = 0; nt < 4; nt++)
                LDSM4(bkh[nt], kvb + bKrow + (nt*16) * FSTRIDE + ks * 32);
            #pragma unroll
            for (int nt = 0; nt < 4; nt++) {
                MMA16816(s[nt*2+0], qf[ks], bkh[nt][0], bkh[nt][1]);
                MMA16816(s[nt*2+1], qf[ks], bkh[nt][2], bkh[nt][3]);
            }
        }

        float mx0 = -1e30f, mx1 = -1e30f;
        #pragma unroll
        for (int j = 0; j < 8; j++) {
            mx0 = fmaxf(mx0, fmaxf(s[j][0], s[j][1]));
            mx1 = fmaxf(mx1, fmaxf(s[j][2], s[j][3]));
        }
        mx0 = fmaxf(mx0, __shfl_xor_sync(0xffffffffu, mx0, 1));
        mx0 = fmaxf(mx0, __shfl_xor_sync(0xffffffffu, mx0, 2));
        mx1 = fmaxf(mx1, __shfl_xor_sync(0xffffffffu, mx1, 1));
        mx1 = fmaxf(mx1, __shfl_xor_sync(0xffffffffu, mx1, 2));
        const float mn0 = fmaxf(m0, mx0), mn1 = fmaxf(m1, mx1);
        const float corr0 = __expf(m0 - mn0), corr1 = __expf(m1 - mn1);
        m0 = mn0; m1 = mn1;

        float sum0 = 0.0f, sum1 = 0.0f;
        uint32_t ap[16];
        #pragma unroll
        for (int j = 0; j < 8; j++) {
            float p0 = __expf(s[j][0] - mn0), p1 = __expf(s[j][1] - mn0);
            float p2 = __expf(s[j][2] - mn1), p3 = __expf(s[j][3] - mn1);
            sum0 += p0 + p1; sum1 += p2 + p3;
            __half2 hi01 = __halves2half2(__float2half(p0), __float2half(p1));
            __half2 hi23 = __halves2half2(__float2half(p2), __float2half(p3));
            const int t4 = (j >> 1) * 4 + (j & 1) * 2;
            ap[t4 + 0] = *reinterpret_cast<uint32_t*>(&hi01);
            ap[t4 + 1] = *reinterpret_cast<uint32_t*>(&hi23);
        }
        sum0 += __shfl_xor_sync(0xffffffffu, sum0, 1);
        sum0 += __shfl_xor_sync(0xffffffffu, sum0, 2);
        sum1 += __shfl_xor_sync(0xffffffffu, sum1, 1);
        sum1 += __shfl_xor_sync(0xffffffffu, sum1, 2);
        l0 = l0 * corr0 + sum0;
        l1 = l1 * corr1 + sum1;
        #pragma unroll
        for (int j = 0; j < 8; j++) {
            o[j][0] *= corr0; o[j][1] *= corr0;
            o[j][2] *= corr1; o[j][3] *= corr1;
        }

        #pragma unroll
        for (int t = 0; t < 4; t++) {
            uint32_t bvh[4][4];
            #pragma unroll
            for (int ns = 0; ns < 4; ns++)
                LDSM4T(bvh[ns], kvb + FTILEB + bVrow + (t*16) * FSTRIDE + ns * 32);
            #pragma unroll
            for (int ns = 0; ns < 4; ns++) {
                MMA16816(o[ns*2+0], ap + t*4, bvh[ns][0], bvh[ns][1]);
                MMA16816(o[ns*2+1], ap + t*4, bvh[ns][2], bvh[ns][3]);
            }
        }
    }

    const float inv0 = 1.0f / l0, inv1 = 1.0f / l1;
    const int r0 = qb + w*16 + (lane >> 2);
    const int gr0 = (bh >> 4) * SEQ + r0;
    const int colb = (bh & 15) * D_HEAD + 2 * (lane & 3);
    #pragma unroll
    for (int j = 0; j < 8; j++) {
        const int col = colb + j * 8;
        __half2 h0, h1;
        h0.x = __float2half(o[j][0] * inv0);
        h0.y = __float2half(o[j][1] * inv0);
        h1.x = __float2half(o[j][2] * inv1);
        h1.y = __float2half(o[j][3] * inv1);
        *reinterpret_cast<__half2*>(outH + (size_t)gr0 * D_MODEL + col) = h0;
        *reinterpret_cast<__half2*>(outH + (size_t)(gr0 + 8) * D_MODEL + col) = h1;
    }
}

// ---------------- launch --------------------------------------------------
extern "C" void kernel_launch(void* const* d_in, const int* in_sizes, int n_in,
                              void* d_out, int out_size)
{
    const float* x    = (const float*)d_in[0];
    const float* wq   = (const float*)d_in[1];
    const float* wk   = (const float*)d_in[2];
    const float* wv   = (const float*)d_in[3];
    const float* wo   = (const float*)d_in[4];
    const float* w1   = (const float*)d_in[5];
    const float* b1   = (const float*)d_in[6];
    const float* w2   = (const float*)d_in[7];
    const float* b2   = (const float*)d_in[8];
    const float* ln1g = (const float*)d_in[9];
    const float* ln1b = (const float*)d_in[10];
    const float* ln2g = (const float*)d_in[11];
    const float* ln2b = (const float*)d_in[12];
    float* out = (float*)d_out;

    __half *h, *h2, *at, *ff, *Bqkv, *Bo, *B1, *B2, *qkv;
    float *x1;
    cudaGetSymbolAddress((void**)&h,    g_h);
    cudaGetSymbolAddress((void**)&h2,   g_h2);
    cudaGetSymbolAddress((void**)&at,   g_at);
    cudaGetSymbolAddress((void**)&ff,   g_ff);
    cudaGetSymbolAddress((void**)&Bqkv, g_Bqkv);
    cudaGetSymbolAddress((void**)&Bo,   g_Bo);
    cudaGetSymbolAddress((void**)&B1,   g_B1);
    cudaGetSymbolAddress((void**)&B2,   g_B2);
    cudaGetSymbolAddress((void**)&qkv,  g_qkv);
    cudaGetSymbolAddress((void**)&x1,   g_x1);

    cudaFuncSetAttribute(hmma_gemm<1>, cudaFuncAttributeMaxDynamicSharedMemorySize, SMEM_GEMM_BYTES);
    cudaFuncSetAttribute(hmma_gemm<2>, cudaFuncAttributeMaxDynamicSharedMemorySize, SMEM_GEMM_BYTES);
    cudaFuncSetAttribute(hmma_gemm<3>, cudaFuncAttributeMaxDynamicSharedMemorySize, SMEM_GEMM_BYTES);
    cudaFuncSetAttribute(hmma_gemm<4>, cudaFuncAttributeMaxDynamicSharedMemorySize, SMEM_GEMM_BYTES);
    cudaFuncSetAttribute(flash_mma,    cudaFuncAttributeMaxDynamicSharedMemorySize, SMEM_FLASH_BYTES);

    const dim3 blkG(256);
    const dim3 blk(256);
    const dim3 gQKV(QKVS/BN,    NROWS/BM);   // (24, 32) = 768 CTAs
    const dim3 gP  (D_MODEL/BN, NROWS/BM);   // (8, 32)  = 256 CTAs
    const dim3 gF1 (D_FF/BN,    NROWS/BM);   // (32, 32) = 1024 CTAs
    const dim3 gAttn(SEQ/64, BATCH*N_HEADS); // (32, 32)

    conv_qkv<<<dim3(D_MODEL*D_MODEL/4/256, 3), blk>>>(wq, wk, wv, Bqkv);             // 1
    ln_half<<<NROWS, blk>>>(x, ln1g, ln1b, h);                                       // 2
    conv_single<<<(D_FF*D_MODEL/4+255)/256, blk>>>(w1, B1, D_FF*D_MODEL);            // 3
    hmma_gemm<4><<<gQKV, blkG, SMEM_GEMM_BYTES>>>(h, Bqkv, nullptr, nullptr,
                                                  nullptr, qkv, QKVS, D_MODEL);      // 4 <- profiled
    conv_single<<<(D_MODEL*D_MODEL/4+255)/256, blk>>>(wo, Bo, D_MODEL*D_MODEL);      // 5
    conv_single<<<(D_MODEL*D_FF/4+255)/256,    blk>>>(w2, B2, D_MODEL*D_FF);         // 6
    flash_mma<<<gAttn, dim3(128), SMEM_FLASH_BYTES>>>(qkv, at);                      // 7
    hmma_gemm<1><<<gP, blkG, SMEM_GEMM_BYTES>>>(at, Bo, nullptr, x, x1,
                                               nullptr, D_MODEL, D_MODEL);           // 8
    ln_half<<<NROWS, blk>>>(x1, ln2g, ln2b, h2);                                     // 9
    hmma_gemm<2><<<gF1, blkG, SMEM_GEMM_BYTES>>>(h2, B1, b1, nullptr, nullptr,
                                               ff, D_FF, D_MODEL);                   // 10
    hmma_gemm<3><<<gP, blkG, SMEM_GEMM_BYTES>>>(ff, B2, b2, x1, out,
                                               nullptr, D_MODEL, D_FF);              // 11
}

// round 15
// speedup vs baseline: 1.1880x; 1.1040x over previous
#include <cuda_runtime.h>
#include <cuda_fp16.h>
#include <math.h>
#include <cstdint>

#define D_MODEL 1024
#define D_FF    4096
#define N_HEADS 16
#define D_HEAD  64
#define BATCH   2
#define SEQ     2048
#define NROWS   (BATCH*SEQ)   /* 4096 */
#define QKVS    (3*D_MODEL)   /* 3072 */

// ---------------- scratch (device globals; no allocation allowed) ----------
__device__ __half g_h    [NROWS * D_MODEL];
__device__ __half g_h2   [NROWS * D_MODEL];
__device__ __half g_at   [NROWS * D_MODEL];
__device__ __half g_ff   [NROWS * D_FF];
__device__ __half g_Bqkv [QKVS * D_MODEL];     // wq(*0.125)|wk|wv rows
__device__ __half g_Bo   [D_MODEL * D_MODEL];
__device__ __half g_B1   [D_FF * D_MODEL];
__device__ __half g_B2   [D_MODEL * D_FF];
__device__ __half g_qkv  [NROWS * QKVS];       // q|k|v packed per row
__device__ float  g_x1   [NROWS * D_MODEL];

// ================= PTX helpers =============================================
__device__ __forceinline__ uint32_t smem_u32(const void* p) {
    uint32_t a;
    asm("{ .reg .u64 t; cvta.to.shared.u64 t, %1; cvt.u32.u64 %0, t; }" : "=r"(a) : "l"(p));
    return a;
}
__device__ __forceinline__ void cp16(uint32_t s, const void* g) {
    asm volatile("cp.async.cg.shared.global [%0], [%1], 16;" :: "r"(s), "l"(g));
}
#define CP_COMMIT() asm volatile("cp.async.commit_group;" ::: "memory")
#define CP_WAIT(n)  asm volatile("cp.async.wait_group %0;" :: "n"(n) : "memory")

#define LDSM4(r, a) \
    asm volatile("ldmatrix.sync.aligned.m8n8.x4.shared.b16 {%0,%1,%2,%3}, [%4];" \
        : "=r"((r)[0]), "=r"((r)[1]), "=r"((r)[2]), "=r"((r)[3]) : "r"(a))
#define LDSM4T(r, a) \
    asm volatile("ldmatrix.sync.aligned.m8n8.x4.trans.shared.b16 {%0,%1,%2,%3}, [%4];" \
        : "=r"((r)[0]), "=r"((r)[1]), "=r"((r)[2]), "=r"((r)[3]) : "r"(a))

#define MMA16816(c, a, b0, b1) \
    asm volatile("mma.sync.aligned.m16n8k16.row.col.f32.f16.f16.f32 " \
        "{%0,%1,%2,%3}, {%4,%5,%6,%7}, {%8,%9}, {%0,%1,%2,%3};" \
        : "+f"((c)[0]), "+f"((c)[1]), "+f"((c)[2]), "+f"((c)[3]) \
        : "r"((a)[0]), "r"((a)[1]), "r"((a)[2]), "r"((a)[3]), "r"(b0), "r"(b1))

// -- GEMM tiling: BM=BN=128, BK=64, 3 stages, 8 warps 2x4, 64x32 warp tiles -
#define BM 128
#define BN 128
#define BK 64
#define GRS 144                            /* smem row stride bytes (72 fp16) */
#define GT  (128 * GRS)                    /* one tile: 18432 B */
#define GSTAGEB (2 * GT)                   /* A,B: 36864 B */
#define SMEM_GEMM_BYTES (3 * GSTAGEB)      /* 110592 B */

__device__ __forceinline__ float gelu_exact(float v) {
    return 0.5f * v * (1.0f + erff(v * 0.70710678118654752f));
}

// ===== HMMA GEMM: C[M,N] = A[M,K] * B[N,K]^T  (fp16 in, fp32 accum) ========
// EPI: 1 +res->fp32, 2 gelu(+bias)->fp16, 3 +bias+res->fp32, 4 ->fp16
template<int EPI>
__global__ __launch_bounds__(256, 2) void hmma_gemm(
    const __half* __restrict__ A,
    const __half* __restrict__ B,
    const float* __restrict__ bias,
    const float* __restrict__ res,
    float* __restrict__ C,
    __half* __restrict__ CH,
    int N, int K)
{
    extern __shared__ char smem[];
    const uint32_t sbase = smem_u32(smem);
    const int tid  = threadIdx.x;
    const int wid  = tid >> 5, lane = tid & 31;
    const int wm   = wid >> 2, wn = wid & 3;       // 2 x 4 warps, 64x32 tiles
    const int rowB = blockIdx.y * BM, colB = blockIdx.x * BN;

    const __half* srcs[2] = { A + (size_t)rowB * K, B + (size_t)colB * K };

    auto load_stage = [&](int s, int kt) {
        const int k0 = kt * BK;
        const uint32_t st = sbase + s * GSTAGEB;
        #pragma unroll
        for (int i = 0; i < 8; i++) {
            const int tile = i >> 2;                  // 0..1 (const per i)
            const int within = (i & 3) * 256 + tid;   // 0..1023
            const int r = within >> 3, seg = within & 7;
            cp16(st + tile * GT + r * GRS + seg * 16,
                 srcs[tile] + (size_t)r * K + k0 + seg * 8);
        }
        CP_COMMIT();
    };

    float acc[4][4][4];
    #pragma unroll
    for (int i = 0; i < 4; i++)
        #pragma unroll
        for (int j = 0; j < 4; j++)
            #pragma unroll
            for (int q = 0; q < 4; q++) acc[i][j][q] = 0.0f;

    const int niter = K / BK;
    load_stage(0, 0);
    load_stage(1, 1);

    for (int t = 0; t < niter; t++) {
        CP_WAIT(1);
        __syncthreads();
        if (t + 2 < niter) load_stage((t + 2) % 3, t + 2);

        const uint32_t st = sbase + (t % 3) * GSTAGEB;
        const uint32_t sA = st, sB = st + GT;

        #pragma unroll
        for (int ks = 0; ks < 4; ks++) {
            const uint32_t aoff = (wm*64 + (lane & 15)) * GRS
                                + (ks*16 + (lane >> 4) * 8) * 2;
            const uint32_t boff = (wn*32 + (lane >> 4) * 8 + (lane & 7)) * GRS
                                + (ks*16 + ((lane >> 3) & 1) * 8) * 2;
            uint32_t a[4][4], b[2][4];
            #pragma unroll
            for (int mi = 0; mi < 4; mi++) LDSM4(a[mi], sA + aoff + mi*16*GRS);
            #pragma unroll
            for (int nt = 0; nt < 2; nt++) LDSM4(b[nt], sB + boff + nt*16*GRS);
            #pragma unroll
            for (int mi = 0; mi < 4; mi++)
                #pragma unroll
                for (int nt = 0; nt < 2; nt++) {
                    MMA16816(acc[mi][nt*2+0], a[mi], b[nt][0], b[nt][1]);
                    MMA16816(acc[mi][nt*2+1], a[mi], b[nt][2], b[nt][3]);
                }
        }
        // no trailing sync: next iter's top barrier orders stage reuse
    }

    const int g  = lane >> 2;
    const int tq = lane & 3;
    #pragma unroll
    for (int mi = 0; mi < 4; mi++) {
        #pragma unroll
        for (int half = 0; half < 2; half++) {
            const int gr = rowB + wm*64 + mi*16 + g + half*8;
            #pragma unroll
            for (int ni = 0; ni < 4; ni++) {
                const int gc = colB + wn*32 + ni*8 + tq*2;
                float v0 = acc[mi][ni][half*2+0];
                float v1 = acc[mi][ni][half*2+1];
                if (EPI == 1) {
                    const float2 r2 = *reinterpret_cast<const float2*>(res + (size_t)gr * N + gc);
                    *reinterpret_cast<float2*>(C + (size_t)gr * N + gc) =
                        make_float2(v0 + r2.x, v1 + r2.y);
                } else if (EPI == 3) {
                    const float2 r2 = *reinterpret_cast<const float2*>(res + (size_t)gr * N + gc);
                    *reinterpret_cast<float2*>(C + (size_t)gr * N + gc) =
                        make_float2(v0 + bias[gc] + r2.x, v1 + bias[gc + 1] + r2.y);
                } else {
                    float s0 = v0, s1 = v1;
                    if (EPI == 2) {
                        s0 = gelu_exact(v0 + bias[gc]);
                        s1 = gelu_exact(v1 + bias[gc + 1]);
                    }
                    __half2 h2v;
                    h2v.x = __float2half(s0);
                    h2v.y = __float2half(s1);
                    *reinterpret_cast<__half2*>(CH + (size_t)gr * N + gc) = h2v;
                }
            }
        }
    }
}

// ---------------- layernorm -> fp16 ----------------------------------------
__global__ __launch_bounds__(256) void ln_half(const float* __restrict__ x,
        const float* __restrict__ g, const float* __restrict__ b,
        __half* __restrict__ H)
{
    __shared__ float red[256];
    const int row = blockIdx.x, t = threadIdx.x;
    const float4 v = reinterpret_cast<const float4*>(x + (size_t)row * D_MODEL)[t];
    red[t] = v.x + v.y + v.z + v.w;
    __syncthreads();
    #pragma unroll
    for (int o = 128; o > 0; o >>= 1) { if (t < o) red[t] += red[t + o]; __syncthreads(); }
    const float mu = red[0] * (1.0f / D_MODEL);
    __syncthreads();
    const float dx = v.x - mu, dy = v.y - mu, dz = v.z - mu, dw = v.w - mu;
    red[t] = dx*dx + dy*dy + dz*dz + dw*dw;
    __syncthreads();
    #pragma unroll
    for (int o = 128; o > 0; o >>= 1) { if (t < o) red[t] += red[t + o]; __syncthreads(); }
    const float rs = rsqrtf(red[0] * (1.0f / D_MODEL) + 1e-5f);
    const float4 gv = reinterpret_cast<const float4*>(g)[t];
    const float4 bv = reinterpret_cast<const float4*>(b)[t];
    __half h[4] = {
        __float2half(dx*rs*gv.x + bv.x), __float2half(dy*rs*gv.y + bv.y),
        __float2half(dz*rs*gv.z + bv.z), __float2half(dw*rs*gv.w + bv.w) };
    *reinterpret_cast<uint2*>(H + (size_t)row * D_MODEL + t * 4) =
        *reinterpret_cast<uint2*>(h);
}

// ---------------- fp32 -> fp16 converters ----------------------------------
__global__ __launch_bounds__(256) void conv_single(const float* __restrict__ src,
        __half* __restrict__ H, int total)
{
    const int i4 = blockIdx.x * 256 + threadIdx.x;
    if (i4 * 4 >= total) return;
    const float4 v = reinterpret_cast<const float4*>(src)[i4];
    __half h[4] = { __float2half(v.x), __float2half(v.y),
                    __float2half(v.z), __float2half(v.w) };
    *reinterpret_cast<uint2*>(H + (size_t)i4 * 4) = *reinterpret_cast<uint2*>(h);
}

// wq (scaled 0.125) | wk | wv -> one [3072 x 1024] fp16 buffer
__global__ __launch_bounds__(256) void conv_qkv(const float* __restrict__ wq,
        const float* __restrict__ wk, const float* __restrict__ wv,
        __half* __restrict__ dst)
{
    const int y = blockIdx.y;
    const float* src = (y == 0) ? wq : ((y == 1) ? wk : wv);
    const float sc = (y == 0) ? 0.125f : 1.0f;
    const int i4 = blockIdx.x * 256 + threadIdx.x;   // 1M/4 elems
    const float4 v = reinterpret_cast<const float4*>(src)[i4];
    __half h[4] = { __float2half(v.x * sc), __float2half(v.y * sc),
                    __float2half(v.z * sc), __float2half(v.w * sc) };
    *reinterpret_cast<uint2*>(dst + (size_t)y * D_MODEL * D_MODEL + (size_t)i4 * 4) =
        *reinterpret_cast<uint2*>(h);
}

// ========== flash attention (fp16, BQ=64, TK=64, 4 warps) ==================
// reads q/k/v from packed [NROWS x 3072] buffer
#define FSTRIDE 144
#define FTILEB  (64 * FSTRIDE)         /* 9216 */
#define FQ_BYTES (FTILEB)
#define FKV_BYTES (2 * FTILEB)
#define SMEM_FLASH_BYTES (FQ_BYTES + 2 * FKV_BYTES)  /* 46080 */

__global__ __launch_bounds__(128, 2) void flash_mma(
        const __half* __restrict__ QKV, __half* __restrict__ outH)
{
    extern __shared__ char smem[];
    const uint32_t sb = smem_u32(smem);
    const int tid = threadIdx.x;
    const int w = tid >> 5, lane = tid & 31;
    const int bh = blockIdx.y;                       // 0..31
    const size_t base = (size_t)(bh >> 4) * SEQ * QKVS + (size_t)(bh & 15) * D_HEAD;
    const int qb = blockIdx.x * 64;

    #pragma unroll
    for (int i = 0; i < 4; i++) {
        const int c = i * 128 + tid;
        const int row = c >> 3, seg = c & 7;
        cp16(sb + row * FSTRIDE + seg * 16,
             QKV + base + (size_t)(qb + row) * QKVS + seg * 8);
    }
    auto load_kv = [&](int buf, int kt) {
        const uint32_t kvb = sb + FQ_BYTES + buf * FKV_BYTES;
        #pragma unroll
        for (int i = 0; i < 4; i++) {
            const int c = i * 128 + tid;
            const int row = c >> 3, seg = c & 7;
            const size_t goff = base + (size_t)(kt + row) * QKVS + seg * 8;
            const uint32_t soff = row * FSTRIDE + seg * 16;
            cp16(kvb + 0*FTILEB + soff, QKV + goff + D_MODEL);       // K
            cp16(kvb + 1*FTILEB + soff, QKV + goff + 2 * D_MODEL);   // V
        }
        CP_COMMIT();
    };
    load_kv(0, 0);

    float m0 = -1e30f, m1 = -1e30f, l0 = 0.0f, l1 = 0.0f;
    float o[8][4];
    #pragma unroll
    for (int j = 0; j < 8; j++)
        #pragma unroll
        for (int q = 0; q < 4; q++) o[j][q] = 0.0f;

    const uint32_t aQrow = (w*16 + (lane & 15)) * FSTRIDE + (lane >> 4) * 16;
    const uint32_t bKrow = ((lane >> 4) * 8 + (lane & 7)) * FSTRIDE + ((lane >> 3) & 1) * 16;
    const uint32_t bVrow = (lane & 15) * FSTRIDE + (lane >> 4) * 16;

    uint32_t qf[4][4];

    for (int ti = 0; ti < SEQ / 64; ti++) {
        CP_WAIT(0);
        __syncthreads();
        if (ti + 1 < SEQ / 64) load_kv((ti + 1) & 1, (ti + 1) * 64);
        if (ti == 0) {
            #pragma unroll
            for (int ks = 0; ks < 4; ks++) LDSM4(qf[ks], sb + aQrow + ks * 32);
        }
        const uint32_t kvb = sb + FQ_BYTES + (ti & 1) * FKV_BYTES;

        float s[8][4];
        #pragma unroll
        for (int j = 0; j < 8; j++)
            #pragma unroll
            for (int q = 0; q < 4; q++) s[j][q] = 0.0f;
        #pragma unroll
        for (int ks = 0; ks < 4; ks++) {
            uint32_t bkh[4][4];
            #pragma unroll
            for (int nt = 0; nt < 4; nt++)
                LDSM4(bkh[nt], kvb + bKrow + (nt*16) * FSTRIDE + ks * 32);
            #pragma unroll
            for (int nt = 0; nt < 4; nt++) {
                MMA16816(s[nt*2+0], qf[ks], bkh[nt][0], bkh[nt][1]);
                MMA16816(s[nt*2+1], qf[ks], bkh[nt][2], bkh[nt][3]);
            }
        }

        float mx0 = -1e30f, mx1 = -1e30f;
        #pragma unroll
        for (int j = 0; j < 8; j++) {
            mx0 = fmaxf(mx0, fmaxf(s[j][0], s[j][1]));
            mx1 = fmaxf(mx1, fmaxf(s[j][2], s[j][3]));
        }
        mx0 = fmaxf(mx0, __shfl_xor_sync(0xffffffffu, mx0, 1));
        mx0 = fmaxf(mx0, __shfl_xor_sync(0xffffffffu, mx0, 2));
        mx1 = fmaxf(mx1, __shfl_xor_sync(0xffffffffu, mx1, 1));
        mx1 = fmaxf(mx1, __shfl_xor_sync(0xffffffffu, mx1, 2));
        const float mn0 = fmaxf(m0, mx0), mn1 = fmaxf(m1, mx1);
        const float corr0 = __expf(m0 - mn0), corr1 = __expf(m1 - mn1);
        m0 = mn0; m1 = mn1;

        float sum0 = 0.0f, sum1 = 0.0f;
        uint32_t ap[16];
        #pragma unroll
        for (int j = 0; j < 8; j++) {
            float p0 = __expf(s[j][0] - mn0), p1 = __expf(s[j][1] - mn0);
            float p2 = __expf(s[j][2] - mn1), p3 = __expf(s[j][3] - mn1);
            sum0 += p0 + p1; sum1 += p2 + p3;
            __half2 hi01 = __halves2half2(__float2half(p0), __float2half(p1));
            __half2 hi23 = __halves2half2(__float2half(p2), __float2half(p3));
            const int t4 = (j >> 1) * 4 + (j & 1) * 2;
            ap[t4 + 0] = *reinterpret_cast<uint32_t*>(&hi01);
            ap[t4 + 1] = *reinterpret_cast<uint32_t*>(&hi23);
        }
        sum0 += __shfl_xor_sync(0xffffffffu, sum0, 1);
        sum0 += __shfl_xor_sync(0xffffffffu, sum0, 2);
        sum1 += __shfl_xor_sync(0xffffffffu, sum1, 1);
        sum1 += __shfl_xor_sync(0xffffffffu, sum1, 2);
        l0 = l0 * corr0 + sum0;
        l1 = l1 * corr1 + sum1;
        #pragma unroll
        for (int j = 0; j < 8; j++) {
            o[j][0] *= corr0; o[j][1] *= corr0;
            o[j][2] *= corr1; o[j][3] *= corr1;
        }

        #pragma unroll
        for (int t = 0; t < 4; t++) {
            uint32_t bvh[4][4];
            #pragma unroll
            for (int ns = 0; ns < 4; ns++)
                LDSM4T(bvh[ns], kvb + FTILEB + bVrow + (t*16) * FSTRIDE + ns * 32);
            #pragma unroll
            for (int ns = 0; ns < 4; ns++) {
                MMA16816(o[ns*2+0], ap + t*4, bvh[ns][0], bvh[ns][1]);
                MMA16816(o[ns*2+1], ap + t*4, bvh[ns][2], bvh[ns][3]);
            }
        }
    }

    const float inv0 = 1.0f / l0, inv1 = 1.0f / l1;
    const int r0 = qb + w*16 + (lane >> 2);
    const int gr0 = (bh >> 4) * SEQ + r0;
    const int colb = (bh & 15) * D_HEAD + 2 * (lane & 3);
    #pragma unroll
    for (int j = 0; j < 8; j++) {
        const int col = colb + j * 8;
        __half2 h0, h1;
        h0.x = __float2half(o[j][0] * inv0);
        h0.y = __float2half(o[j][1] * inv0);
        h1.x = __float2half(o[j][2] * inv1);
        h1.y = __float2half(o[j][3] * inv1);
        *reinterpret_cast<__half2*>(outH + (size_t)gr0 * D_MODEL + col) = h0;
        *reinterpret_cast<__half2*>(outH + (size_t)(gr0 + 8) * D_MODEL + col) = h1;
    }
}

// ---------------- launch --------------------------------------------------
extern "C" void kernel_launch(void* const* d_in, const int* in_sizes, int n_in,
                              void* d_out, int out_size)
{
    const float* x    = (const float*)d_in[0];
    const float* wq   = (const float*)d_in[1];
    const float* wk   = (const float*)d_in[2];
    const float* wv   = (const float*)d_in[3];
    const float* wo   = (const float*)d_in[4];
    const float* w1   = (const float*)d_in[5];
    const float* b1   = (const float*)d_in[6];
    const float* w2   = (const float*)d_in[7];
    const float* b2   = (const float*)d_in[8];
    const float* ln1g = (const float*)d_in[9];
    const float* ln1b = (const float*)d_in[10];
    const float* ln2g = (const float*)d_in[11];
    const float* ln2b = (const float*)d_in[12];
    float* out = (float*)d_out;

    __half *h, *h2, *at, *ff, *Bqkv, *Bo, *B1, *B2, *qkv;
    float *x1;
    cudaGetSymbolAddress((void**)&h,    g_h);
    cudaGetSymbolAddress((void**)&h2,   g_h2);
    cudaGetSymbolAddress((void**)&at,   g_at);
    cudaGetSymbolAddress((void**)&ff,   g_ff);
    cudaGetSymbolAddress((void**)&Bqkv, g_Bqkv);
    cudaGetSymbolAddress((void**)&Bo,   g_Bo);
    cudaGetSymbolAddress((void**)&B1,   g_B1);
    cudaGetSymbolAddress((void**)&B2,   g_B2);
    cudaGetSymbolAddress((void**)&qkv,  g_qkv);
    cudaGetSymbolAddress((void**)&x1,   g_x1);

    cudaFuncSetAttribute(hmma_gemm<1>, cudaFuncAttributeMaxDynamicSharedMemorySize, SMEM_GEMM_BYTES);
    cudaFuncSetAttribute(hmma_gemm<2>, cudaFuncAttributeMaxDynamicSharedMemorySize, SMEM_GEMM_BYTES);
    cudaFuncSetAttribute(hmma_gemm<3>, cudaFuncAttributeMaxDynamicSharedMemorySize, SMEM_GEMM_BYTES);
    cudaFuncSetAttribute(hmma_gemm<4>, cudaFuncAttributeMaxDynamicSharedMemorySize, SMEM_GEMM_BYTES);
    cudaFuncSetAttribute(flash_mma,    cudaFuncAttributeMaxDynamicSharedMemorySize, SMEM_FLASH_BYTES);

    const dim3 blkG(256);
    const dim3 blk(256);
    const dim3 gQKV(QKVS/BN,    NROWS/BM);   // (24, 32) = 768 CTAs
    const dim3 gP  (D_MODEL/BN, NROWS/BM);   // (8, 32)  = 256 CTAs
    const dim3 gF1 (D_FF/BN,    NROWS/BM);   // (32, 32) = 1024 CTAs
    const dim3 gAttn(SEQ/64, BATCH*N_HEADS); // (32, 32)

    conv_qkv<<<dim3(D_MODEL*D_MODEL/4/256, 3), blk>>>(wq, wk, wv, Bqkv);             // 1
    ln_half<<<NROWS, blk>>>(x, ln1g, ln1b, h);                                       // 2
    conv_single<<<(D_FF*D_MODEL/4+255)/256, blk>>>(w1, B1, D_FF*D_MODEL);            // 3
    hmma_gemm<4><<<gQKV, blkG, SMEM_GEMM_BYTES>>>(h, Bqkv, nullptr, nullptr,
                                                  nullptr, qkv, QKVS, D_MODEL);      // 4 <- profiled
    conv_single<<<(D_MODEL*D_MODEL/4+255)/256, blk>>>(wo, Bo, D_MODEL*D_MODEL);      // 5
    conv_single<<<(D_MODEL*D_FF/4+255)/256,    blk>>>(w2, B2, D_MODEL*D_FF);         // 6
    flash_mma<<<gAttn, dim3(128), SMEM_FLASH_BYTES>>>(qkv, at);                      // 7
    hmma_gemm<1><<<gP, blkG, SMEM_GEMM_BYTES>>>(at, Bo, nullptr, x, x1,
                                               nullptr, D_MODEL, D_MODEL);           // 8
    ln_half<<<NROWS, blk>>>(x1, ln2g, ln2b, h2);                                     // 9
    hmma_gemm<2><<<gF1, blkG, SMEM_GEMM_BYTES>>>(h2, B1, b1, nullptr, nullptr,
                                               ff, D_FF, D_MODEL);                   // 10
    hmma_gemm<3><<<gP, blkG, SMEM_GEMM_BYTES>>>(ff, B2, b2, x1, out,
                                               nullptr, D_MODEL, D_FF);              // 11
}

// round 16
// speedup vs baseline: 1.2353x; 1.0398x over previous
#include <cuda_runtime.h>
#include <cuda_fp16.h>
#include <math.h>
#include <cstdint>

#define D_MODEL 1024
#define D_FF    4096
#define N_HEADS 16
#define D_HEAD  64
#define BATCH   2
#define SEQ     2048
#define NROWS   (BATCH*SEQ)   /* 4096 */
#define QKVS    (3*D_MODEL)   /* 3072 */

// ---------------- scratch (device globals; no allocation allowed) ----------
__device__ __half g_h    [NROWS * D_MODEL];
__device__ __half g_h2   [NROWS * D_MODEL];
__device__ __half g_at   [NROWS * D_MODEL];
__device__ __half g_ff   [NROWS * D_FF];
__device__ __half g_Bqkv [QKVS * D_MODEL];     // wq(*0.125)|wk|wv rows
__device__ __half g_Bo   [D_MODEL * D_MODEL];
__device__ __half g_B1   [D_FF * D_MODEL];
__device__ __half g_B2   [D_MODEL * D_FF];
__device__ __half g_qkv  [NROWS * QKVS];       // q|k|v packed per row
__device__ float  g_x1   [NROWS * D_MODEL];

// ================= PTX helpers =============================================
__device__ __forceinline__ uint32_t smem_u32(const void* p) {
    uint32_t a;
    asm("{ .reg .u64 t; cvta.to.shared.u64 t, %1; cvt.u32.u64 %0, t; }" : "=r"(a) : "l"(p));
    return a;
}
__device__ __forceinline__ void cp16(uint32_t s, const void* g) {
    asm volatile("cp.async.cg.shared.global [%0], [%1], 16;" :: "r"(s), "l"(g));
}
#define CP_COMMIT() asm volatile("cp.async.commit_group;" ::: "memory")
#define CP_WAIT(n)  asm volatile("cp.async.wait_group %0;" :: "n"(n) : "memory")

#define LDSM4(r, a) \
    asm volatile("ldmatrix.sync.aligned.m8n8.x4.shared.b16 {%0,%1,%2,%3}, [%4];" \
        : "=r"((r)[0]), "=r"((r)[1]), "=r"((r)[2]), "=r"((r)[3]) : "r"(a))
#define LDSM4T(r, a) \
    asm volatile("ldmatrix.sync.aligned.m8n8.x4.trans.shared.b16 {%0,%1,%2,%3}, [%4];" \
        : "=r"((r)[0]), "=r"((r)[1]), "=r"((r)[2]), "=r"((r)[3]) : "r"(a))

#define MMA16816(c, a, b0, b1) \
    asm volatile("mma.sync.aligned.m16n8k16.row.col.f32.f16.f16.f32 " \
        "{%0,%1,%2,%3}, {%4,%5,%6,%7}, {%8,%9}, {%0,%1,%2,%3};" \
        : "+f"((c)[0]), "+f"((c)[1]), "+f"((c)[2]), "+f"((c)[3]) \
        : "r"((a)[0]), "r"((a)[1]), "r"((a)[2]), "r"((a)[3]), "r"(b0), "r"(b1))

// -- GEMM tiling: BM=BN=128, BK=64, 3 stages, 8 warps 2x4, 64x32 warp tiles -
#define BM 128
#define BN 128
#define BK 64
#define GRS 144                            /* smem row stride bytes (72 fp16) */
#define GT  (128 * GRS)                    /* one tile: 18432 B */
#define GSTAGEB (2 * GT)                   /* A,B: 36864 B */
#define SMEM_GEMM_BYTES (3 * GSTAGEB)      /* 110592 B */

__device__ __forceinline__ float gelu_exact(float v) {
    return 0.5f * v * (1.0f + erff(v * 0.70710678118654752f));
}

// ===== HMMA GEMM: C[M,N] = A[M,K] * B[N,K]^T  (fp16 in, fp32 accum) ========
// EPI: 1 +res->fp32, 2 gelu(+bias)->fp16, 3 +bias+res->fp32, 4 ->fp16
template<int EPI>
__global__ __launch_bounds__(256, 2) void hmma_gemm(
    const __half* __restrict__ A,
    const __half* __restrict__ B,
    const float* __restrict__ bias,
    const float* __restrict__ res,
    float* __restrict__ C,
    __half* __restrict__ CH,
    int N, int K)
{
    extern __shared__ char smem[];
    const uint32_t sbase = smem_u32(smem);
    const int tid  = threadIdx.x;
    const int wid  = tid >> 5, lane = tid & 31;
    const int wm   = wid >> 2, wn = wid & 3;       // 2 x 4 warps, 64x32 tiles
    const int rowB = blockIdx.y * BM, colB = blockIdx.x * BN;

    const __half* srcs[2] = { A + (size_t)rowB * K, B + (size_t)colB * K };

    auto load_stage = [&](int s, int kt) {
        const int k0 = kt * BK;
        const uint32_t st = sbase + s * GSTAGEB;
        #pragma unroll
        for (int i = 0; i < 8; i++) {
            const int tile = i >> 2;                  // 0..1 (const per i)
            const int within = (i & 3) * 256 + tid;   // 0..1023
            const int r = within >> 3, seg = within & 7;
            cp16(st + tile * GT + r * GRS + seg * 16,
                 srcs[tile] + (size_t)r * K + k0 + seg * 8);
        }
        CP_COMMIT();
    };

    float acc[4][4][4];
    #pragma unroll
    for (int i = 0; i < 4; i++)
        #pragma unroll
        for (int j = 0; j < 4; j++)
            #pragma unroll
            for (int q = 0; q < 4; q++) acc[i][j][q] = 0.0f;

    const int niter = K / BK;
    load_stage(0, 0);
    load_stage(1, 1);

    for (int t = 0; t < niter; t++) {
        CP_WAIT(1);
        __syncthreads();
        if (t + 2 < niter) load_stage((t + 2) % 3, t + 2);

        const uint32_t st = sbase + (t % 3) * GSTAGEB;
        const uint32_t sA = st, sB = st + GT;

        #pragma unroll
        for (int ks = 0; ks < 4; ks++) {
            const uint32_t aoff = (wm*64 + (lane & 15)) * GRS
                                + (ks*16 + (lane >> 4) * 8) * 2;
            const uint32_t boff = (wn*32 + (lane >> 4) * 8 + (lane & 7)) * GRS
                                + (ks*16 + ((lane >> 3) & 1) * 8) * 2;
            uint32_t a[4][4], b[2][4];
            #pragma unroll
            for (int mi = 0; mi < 4; mi++) LDSM4(a[mi], sA + aoff + mi*16*GRS);
            #pragma unroll
            for (int nt = 0; nt < 2; nt++) LDSM4(b[nt], sB + boff + nt*16*GRS);
            #pragma unroll
            for (int mi = 0; mi < 4; mi++)
                #pragma unroll
                for (int nt = 0; nt < 2; nt++) {
                    MMA16816(acc[mi][nt*2+0], a[mi], b[nt][0], b[nt][1]);
                    MMA16816(acc[mi][nt*2+1], a[mi], b[nt][2], b[nt][3]);
                }
        }
        // no trailing sync: next iter's top barrier orders stage reuse
    }

    const int g  = lane >> 2;
    const int tq = lane & 3;
    #pragma unroll
    for (int mi = 0; mi < 4; mi++) {
        #pragma unroll
        for (int half = 0; half < 2; half++) {
            const int gr = rowB + wm*64 + mi*16 + g + half*8;
            #pragma unroll
            for (int ni = 0; ni < 4; ni++) {
                const int gc = colB + wn*32 + ni*8 + tq*2;
                float v0 = acc[mi][ni][half*2+0];
                float v1 = acc[mi][ni][half*2+1];
                if (EPI == 1) {
                    const float2 r2 = *reinterpret_cast<const float2*>(res + (size_t)gr * N + gc);
                    *reinterpret_cast<float2*>(C + (size_t)gr * N + gc) =
                        make_float2(v0 + r2.x, v1 + r2.y);
                } else if (EPI == 3) {
                    const float2 r2 = *reinterpret_cast<const float2*>(res + (size_t)gr * N + gc);
                    *reinterpret_cast<float2*>(C + (size_t)gr * N + gc) =
                        make_float2(v0 + bias[gc] + r2.x, v1 + bias[gc + 1] + r2.y);
                } else {
                    float s0 = v0, s1 = v1;
                    if (EPI == 2) {
                        s0 = gelu_exact(v0 + bias[gc]);
                        s1 = gelu_exact(v1 + bias[gc + 1]);
                    }
                    __half2 h2v;
                    h2v.x = __float2half(s0);
                    h2v.y = __float2half(s1);
                    *reinterpret_cast<__half2*>(CH + (size_t)gr * N + gc) = h2v;
                }
            }
        }
    }
}

// ---------- layernorm -> fp16 : warp-per-row, shuffle reductions -----------
__global__ __launch_bounds__(256) void ln_half(const float* __restrict__ x,
        const float* __restrict__ g, const float* __restrict__ b,
        __half* __restrict__ H)
{
    const int warp = threadIdx.x >> 5, lane = threadIdx.x & 31;
    const int row = blockIdx.x * 8 + warp;
    const float4* xr = reinterpret_cast<const float4*>(x + (size_t)row * D_MODEL);
    float4 v[8];
    float sum = 0.0f;
    #pragma unroll
    for (int i = 0; i < 8; i++) {
        v[i] = xr[lane + i * 32];
        sum += v[i].x + v[i].y + v[i].z + v[i].w;
    }
    #pragma unroll
    for (int o = 16; o > 0; o >>= 1) sum += __shfl_xor_sync(0xffffffffu, sum, o);
    const float mu = sum * (1.0f / D_MODEL);
    float var = 0.0f;
    #pragma unroll
    for (int i = 0; i < 8; i++) {
        v[i].x -= mu; v[i].y -= mu; v[i].z -= mu; v[i].w -= mu;
        var += v[i].x*v[i].x + v[i].y*v[i].y + v[i].z*v[i].z + v[i].w*v[i].w;
    }
    #pragma unroll
    for (int o = 16; o > 0; o >>= 1) var += __shfl_xor_sync(0xffffffffu, var, o);
    const float rs = rsqrtf(var * (1.0f / D_MODEL) + 1e-5f);
    #pragma unroll
    for (int i = 0; i < 8; i++) {
        const int c4 = lane + i * 32;
        const float4 gv = reinterpret_cast<const float4*>(g)[c4];
        const float4 bv = reinterpret_cast<const float4*>(b)[c4];
        __half hh[4] = {
            __float2half(v[i].x*rs*gv.x + bv.x), __float2half(v[i].y*rs*gv.y + bv.y),
            __float2half(v[i].z*rs*gv.z + bv.z), __float2half(v[i].w*rs*gv.w + bv.w) };
        *reinterpret_cast<uint2*>(H + (size_t)row * D_MODEL + c4 * 4) =
            *reinterpret_cast<uint2*>(hh);
    }
}

// ---------------- fp32 -> fp16 converters (MLP-4) --------------------------
__global__ __launch_bounds__(256) void conv_single(const float* __restrict__ src,
        __half* __restrict__ H, int total4)       // total4 = #float4 elements
{
    const int base = blockIdx.x * 1024 + threadIdx.x;
    float4 v[4];
    #pragma unroll
    for (int i = 0; i < 4; i++) v[i] = reinterpret_cast<const float4*>(src)[base + i*256];
    #pragma unroll
    for (int i = 0; i < 4; i++) {
        __half hh[4] = { __float2half(v[i].x), __float2half(v[i].y),
                         __float2half(v[i].z), __float2half(v[i].w) };
        *reinterpret_cast<uint2*>(H + (size_t)(base + i*256) * 4) =
            *reinterpret_cast<uint2*>(hh);
    }
}

// wq (scaled 0.125) | wk | wv -> one [3072 x 1024] fp16 buffer (MLP-4)
__global__ __launch_bounds__(256) void conv_qkv(const float* __restrict__ wq,
        const float* __restrict__ wk, const float* __restrict__ wv,
        __half* __restrict__ dst)
{
    const int y = blockIdx.y;
    const float* src = (y == 0) ? wq : ((y == 1) ? wk : wv);
    const float sc = (y == 0) ? 0.125f : 1.0f;
    const int base = blockIdx.x * 1024 + threadIdx.x;   // float4 index
    __half* out = dst + (size_t)y * D_MODEL * D_MODEL;
    float4 v[4];
    #pragma unroll
    for (int i = 0; i < 4; i++) v[i] = reinterpret_cast<const float4*>(src)[base + i*256];
    #pragma unroll
    for (int i = 0; i < 4; i++) {
        __half hh[4] = { __float2half(v[i].x * sc), __float2half(v[i].y * sc),
                         __float2half(v[i].z * sc), __float2half(v[i].w * sc) };
        *reinterpret_cast<uint2*>(out + (size_t)(base + i*256) * 4) =
            *reinterpret_cast<uint2*>(hh);
    }
}

// ========== flash attention (fp16, BQ=64, TK=64, 4 warps) ==================
#define FSTRIDE 144
#define FTILEB  (64 * FSTRIDE)         /* 9216 */
#define FQ_BYTES (FTILEB)
#define FKV_BYTES (2 * FTILEB)
#define SMEM_FLASH_BYTES (FQ_BYTES + 2 * FKV_BYTES)  /* 46080 */

__global__ __launch_bounds__(128, 2) void flash_mma(
        const __half* __restrict__ QKV, __half* __restrict__ outH)
{
    extern __shared__ char smem[];
    const uint32_t sb = smem_u32(smem);
    const int tid = threadIdx.x;
    const int w = tid >> 5, lane = tid & 31;
    const int bh = blockIdx.y;                       // 0..31
    const size_t base = (size_t)(bh >> 4) * SEQ * QKVS + (size_t)(bh & 15) * D_HEAD;
    const int qb = blockIdx.x * 64;

    #pragma unroll
    for (int i = 0; i < 4; i++) {
        const int c = i * 128 + tid;
        const int row = c >> 3, seg = c & 7;
        cp16(sb + row * FSTRIDE + seg * 16,
             QKV + base + (size_t)(qb + row) * QKVS + seg * 8);
    }
    auto load_kv = [&](int buf, int kt) {
        const uint32_t kvb = sb + FQ_BYTES + buf * FKV_BYTES;
        #pragma unroll
        for (int i = 0; i < 4; i++) {
            const int c = i * 128 + tid;
            const int row = c >> 3, seg = c & 7;
            const size_t goff = base + (size_t)(kt + row) * QKVS + seg * 8;
            const uint32_t soff = row * FSTRIDE + seg * 16;
            cp16(kvb + 0*FTILEB + soff, QKV + goff + D_MODEL);       // K
            cp16(kvb + 1*FTILEB + soff, QKV + goff + 2 * D_MODEL);   // V
        }
        CP_COMMIT();
    };
    load_kv(0, 0);

    float m0 = -1e30f, m1 = -1e30f, l0 = 0.0f, l1 = 0.0f;
    float o[8][4];
    #pragma unroll
    for (int j = 0; j < 8; j++)
        #pragma unroll
        for (int q = 0; q < 4; q++) o[j][q] = 0.0f;

    const uint32_t aQrow = (w*16 + (lane & 15)) * FSTRIDE + (lane >> 4) * 16;
    const uint32_t bKrow = ((lane >> 4) * 8 + (lane & 7)) * FSTRIDE + ((lane >> 3) & 1) * 16;
    const uint32_t bVrow = (lane & 15) * FSTRIDE + (lane >> 4) * 16;

    uint32_t qf[4][4];

    for (int ti = 0; ti < SEQ / 64; ti++) {
        CP_WAIT(0);
        __syncthreads();
        if (ti + 1 < SEQ / 64) load_kv((ti + 1) & 1, (ti + 1) * 64);
        if (ti == 0) {
            #pragma unroll
            for (int ks = 0; ks < 4; ks++) LDSM4(qf[ks], sb + aQrow + ks * 32);
        }
        const uint32_t kvb = sb + FQ_BYTES + (ti & 1) * FKV_BYTES;

        float s[8][4];
        #pragma unroll
        for (int j = 0; j < 8; j++)
            #pragma unroll
            for (int q = 0; q < 4; q++) s[j][q] = 0.0f;
        #pragma unroll
        for (int ks = 0; ks < 4; ks++) {
            uint32_t bkh[4][4];
            #pragma unroll
            for (int nt = 0; nt < 4; nt++)
                LDSM4(bkh[nt], kvb + bKrow + (nt*16) * FSTRIDE + ks * 32);
            #pragma unroll
            for (int nt = 0; nt < 4; nt++) {
                MMA16816(s[nt*2+0], qf[ks], bkh[nt][0], bkh[nt][1]);
                MMA16816(s[nt*2+1], qf[ks], bkh[nt][2], bkh[nt][3]);
            }
        }

        float mx0 = -1e30f, mx1 = -1e30f;
        #pragma unroll
        for (int j = 0; j < 8; j++) {
            mx0 = fmaxf(mx0, fmaxf(s[j][0], s[j][1]));
            mx1 = fmaxf(mx1, fmaxf(s[j][2], s[j][3]));
        }
        mx0 = fmaxf(mx0, __shfl_xor_sync(0xffffffffu, mx0, 1));
        mx0 = fmaxf(mx0, __shfl_xor_sync(0xffffffffu, mx0, 2));
        mx1 = fmaxf(mx1, __shfl_xor_sync(0xffffffffu, mx1, 1));
        mx1 = fmaxf(mx1, __shfl_xor_sync(0xffffffffu, mx1, 2));
        const float mn0 = fmaxf(m0, mx0), mn1 = fmaxf(m1, mx1);
        const float corr0 = __expf(m0 - mn0), corr1 = __expf(m1 - mn1);
        m0 = mn0; m1 = mn1;

        float sum0 = 0.0f, sum1 = 0.0f;
        uint32_t ap[16];
        #pragma unroll
        for (int j = 0; j < 8; j++) {
            float p0 = __expf(s[j][0] - mn0), p1 = __expf(s[j][1] - mn0);
            float p2 = __expf(s[j][2] - mn1), p3 = __expf(s[j][3] - mn1);
            sum0 += p0 + p1; sum1 += p2 + p3;
            __half2 hi01 = __halves2half2(__float2half(p0), __float2half(p1));
            __half2 hi23 = __halves2half2(__float2half(p2), __float2half(p3));
            const int t4 = (j >> 1) * 4 + (j & 1) * 2;
            ap[t4 + 0] = *reinterpret_cast<uint32_t*>(&hi01);
            ap[t4 + 1] = *reinterpret_cast<uint32_t*>(&hi23);
        }
        sum0 += __shfl_xor_sync(0xffffffffu, sum0, 1);
        sum0 += __shfl_xor_sync(0xffffffffu, sum0, 2);
        sum1 += __shfl_xor_sync(0xffffffffu, sum1, 1);
        sum1 += __shfl_xor_sync(0xffffffffu, sum1, 2);
        l0 = l0 * corr0 + sum0;
        l1 = l1 * corr1 + sum1;
        #pragma unroll
        for (int j = 0; j < 8; j++) {
            o[j][0] *= corr0; o[j][1] *= corr0;
            o[j][2] *= corr1; o[j][3] *= corr1;
        }

        #pragma unroll
        for (int t = 0; t < 4; t++) {
            uint32_t bvh[4][4];
            #pragma unroll
            for (int ns = 0; ns < 4; ns++)
                LDSM4T(bvh[ns], kvb + FTILEB + bVrow + (t*16) * FSTRIDE + ns * 32);
            #pragma unroll
            for (int ns = 0; ns < 4; ns++) {
                MMA16816(o[ns*2+0], ap + t*4, bvh[ns][0], bvh[ns][1]);
                MMA16816(o[ns*2+1], ap + t*4, bvh[ns][2], bvh[ns][3]);
            }
        }
    }

    const float inv0 = 1.0f / l0, inv1 = 1.0f / l1;
    const int r0 = qb + w*16 + (lane >> 2);
    const int gr0 = (bh >> 4) * SEQ + r0;
    const int colb = (bh & 15) * D_HEAD + 2 * (lane & 3);
    #pragma unroll
    for (int j = 0; j < 8; j++) {
        const int col = colb + j * 8;
        __half2 h0, h1;
        h0.x = __float2half(o[j][0] * inv0);
        h0.y = __float2half(o[j][1] * inv0);
        h1.x = __float2half(o[j][2] * inv1);
        h1.y = __float2half(o[j][3] * inv1);
        *reinterpret_cast<__half2*>(outH + (size_t)gr0 * D_MODEL + col) = h0;
        *reinterpret_cast<__half2*>(outH + (size_t)(gr0 + 8) * D_MODEL + col) = h1;
    }
}

// ---------------- launch --------------------------------------------------
extern "C" void kernel_launch(void* const* d_in, const int* in_sizes, int n_in,
                              void* d_out, int out_size)
{
    const float* x    = (const float*)d_in[0];
    const float* wq   = (const float*)d_in[1];
    const float* wk   = (const float*)d_in[2];
    const float* wv   = (const float*)d_in[3];
    const float* wo   = (const float*)d_in[4];
    const float* w1   = (const float*)d_in[5];
    const float* b1   = (const float*)d_in[6];
    const float* w2   = (const float*)d_in[7];
    const float* b2   = (const float*)d_in[8];
    const float* ln1g = (const float*)d_in[9];
    const float* ln1b = (const float*)d_in[10];
    const float* ln2g = (const float*)d_in[11];
    const float* ln2b = (const float*)d_in[12];
    float* out = (float*)d_out;

    __half *h, *h2, *at, *ff, *Bqkv, *Bo, *B1, *B2, *qkv;
    float *x1;
    cudaGetSymbolAddress((void**)&h,    g_h);
    cudaGetSymbolAddress((void**)&h2,   g_h2);
    cudaGetSymbolAddress((void**)&at,   g_at);
    cudaGetSymbolAddress((void**)&ff,   g_ff);
    cudaGetSymbolAddress((void**)&Bqkv, g_Bqkv);
    cudaGetSymbolAddress((void**)&Bo,   g_Bo);
    cudaGetSymbolAddress((void**)&B1,   g_B1);
    cudaGetSymbolAddress((void**)&B2,   g_B2);
    cudaGetSymbolAddress((void**)&qkv,  g_qkv);
    cudaGetSymbolAddress((void**)&x1,   g_x1);

    static cudaStream_t s2 = nullptr;
    static cudaEvent_t  e1 = nullptr, e2 = nullptr;
    static bool inited = false;
    if (!inited) {
        cudaStreamCreateWithFlags(&s2, cudaStreamNonBlocking);
        cudaEventCreateWithFlags(&e1, cudaEventDisableTiming);
        cudaEventCreateWithFlags(&e2, cudaEventDisableTiming);
        cudaFuncSetAttribute(hmma_gemm<1>, cudaFuncAttributeMaxDynamicSharedMemorySize, SMEM_GEMM_BYTES);
        cudaFuncSetAttribute(hmma_gemm<2>, cudaFuncAttributeMaxDynamicSharedMemorySize, SMEM_GEMM_BYTES);
        cudaFuncSetAttribute(hmma_gemm<3>, cudaFuncAttributeMaxDynamicSharedMemorySize, SMEM_GEMM_BYTES);
        cudaFuncSetAttribute(hmma_gemm<4>, cudaFuncAttributeMaxDynamicSharedMemorySize, SMEM_GEMM_BYTES);
        cudaFuncSetAttribute(flash_mma,    cudaFuncAttributeMaxDynamicSharedMemorySize, SMEM_FLASH_BYTES);
        inited = true;
    }

    const dim3 blkG(256);
    const dim3 blk(256);
    const dim3 gQKV(QKVS/BN,    NROWS/BM);   // (24, 32) = 768 CTAs
    const dim3 gP  (D_MODEL/BN, NROWS/BM);   // (8, 32)  = 256 CTAs
    const dim3 gF1 (D_FF/BN,    NROWS/BM);   // (32, 32) = 1024 CTAs
    const dim3 gAttn(SEQ/64, BATCH*N_HEADS); // (32, 32)

    // default stream: deps of the qkv GEMM
    ln_half<<<NROWS/8, blk>>>(x, ln1g, ln1b, h);                                     // 1
    conv_qkv<<<dim3(D_MODEL*D_MODEL/4/1024, 3), blk>>>(wq, wk, wv, Bqkv);            // 2

    // fork: w1/wo/w2 conversions run concurrently with qkv GEMM + flash
    cudaEventRecord(e1, 0);
    cudaStreamWaitEvent(s2, e1, 0);
    conv_single<<<D_FF*D_MODEL/4/1024, blk, 0, s2>>>(w1, B1, D_FF*D_MODEL/4);        // 3 (s2)
    hmma_gemm<4><<<gQKV, blkG, SMEM_GEMM_BYTES>>>(h, Bqkv, nullptr, nullptr,
                                                  nullptr, qkv, QKVS, D_MODEL);      // 4 <- profiled
    conv_single<<<D_MODEL*D_MODEL/4/1024, blk, 0, s2>>>(wo, Bo, D_MODEL*D_MODEL/4);  // 5 (s2)
    conv_single<<<D_MODEL*D_FF/4/1024, blk, 0, s2>>>(w2, B2, D_MODEL*D_FF/4);        // 6 (s2)
    cudaEventRecord(e2, s2);

    flash_mma<<<gAttn, dim3(128), SMEM_FLASH_BYTES>>>(qkv, at);                      // 7

    // join before first consumer of Bo/B1/B2
    cudaStreamWaitEvent(0, e2, 0);
    hmma_gemm<1><<<gP, blkG, SMEM_GEMM_BYTES>>>(at, Bo, nullptr, x, x1,
                                               nullptr, D_MODEL, D_MODEL);           // 8
    ln_half<<<NROWS/8, blk>>>(x1, ln2g, ln2b, h2);                                   // 9
    hmma_gemm<2><<<gF1, blkG, SMEM_GEMM_BYTES>>>(h2, B1, b1, nullptr, nullptr,
                                               ff, D_FF, D_MODEL);                   // 10
    hmma_gemm<3><<<gP, blkG, SMEM_GEMM_BYTES>>>(ff, B2, b2, x1, out,
                                               nullptr, D_MODEL, D_FF);              // 11
}